// round 8
// baseline (speedup 1.0000x reference)
#include <cuda_runtime.h>

#define BB   2
#define NN   512
#define DD   256
#define HH   4
#define HDD  64
#define HDH  256

typedef unsigned long long ull;
#define ABS2 0x7fffffff7fffffffULL

__device__ __align__(16) float g_hq[BB*NN*HDH];
__device__ __align__(16) float g_hk[BB*NN*HDH];
__device__ __align__(16) float g_hv[BB*NN*HDH];
__device__ __align__(16) float g_es[BB*HH*NN*NN];   // e scratch, [B,H,N,N]

__device__ __forceinline__ ull add2(ull a, ull b) {
    ull r; asm("add.rn.f32x2 %0, %1, %2;" : "=l"(r) : "l"(a), "l"(b)); return r;
}
__device__ __forceinline__ ull fma2(ull a, ull b, ull c) {
    ull r; asm("fma.rn.f32x2 %0, %1, %2, %3;" : "=l"(r) : "l"(a), "l"(b), "l"(c)); return r;
}
__device__ __forceinline__ ull pack2(float lo, float hi) {
    ull r; asm("mov.b64 %0, {%1, %2};" : "=l"(r) : "f"(lo), "f"(hi)); return r;
}
__device__ __forceinline__ float2 unpack2(ull v) {
    float2 f; asm("mov.b64 {%0, %1}, %2;" : "=f"(f.x), "=f"(f.y) : "l"(v)); return f;
}

// ---------------------------------------------------------------------------
// Kernel 1: projections (round-7 version, balanced 384-block grid)
// ---------------------------------------------------------------------------
__global__ __launch_bounds__(256) void proj_kernel(
    const float* __restrict__ q, const float* __restrict__ k, const float* __restrict__ v,
    const float* __restrict__ wq, const float* __restrict__ bq,
    const float* __restrict__ wv, const float* __restrict__ bv)
{
    __shared__ float sx[2][32][18];
    __shared__ float sw[2][32][128];

    int bid = blockIdx.x;
    int m   = bid >> 7;
    int rem = bid & 127;
    int rt  = rem >> 1;
    int ct  = rem & 1;
    int r0 = rt * 16, c0 = ct * 128;

    const float* src  = (m==0) ? q : (m==1) ? k : v;
    const float* W    = (m<2)  ? wq : wv;
    const float* bias = (m<2)  ? bq : bv;
    float* dst        = (m==0) ? g_hq : (m==1) ? g_hk : g_hv;

    int tid = threadIdx.x;
    int ry  = tid >> 5;
    int cx  = tid & 31;

    float4 b4 = *(const float4*)&bias[c0 + cx*4];
    float4 accA = b4, accB = b4;

    int xrow = tid >> 3, xkg = tid & 7;

    float4 xr = make_float4(0.f,0.f,0.f,0.f);
    if (tid < 128) xr = *(const float4*)&src[(size_t)(r0 + xrow)*DD + xkg*4];
    float4 wr[4];
    #pragma unroll
    for (int j = 0; j < 4; j++) {
        int idx = tid + j*256;
        wr[j] = *(const float4*)&W[(size_t)(idx>>5)*DD + c0 + (idx&31)*4];
    }

    if (tid < 128) {
        sx[0][xkg*4+0][xrow] = xr.x;
        sx[0][xkg*4+1][xrow] = xr.y;
        sx[0][xkg*4+2][xrow] = xr.z;
        sx[0][xkg*4+3][xrow] = xr.w;
    }
    #pragma unroll
    for (int j = 0; j < 4; j++) {
        int idx = tid + j*256;
        *(float4*)&sw[0][idx>>5][(idx&31)*4] = wr[j];
    }
    __syncthreads();

    #pragma unroll 1
    for (int c = 0; c < 8; c++) {
        int buf = c & 1;
        if (c < 7) {
            int dbase = (c + 1) * 32;
            if (tid < 128) xr = *(const float4*)&src[(size_t)(r0 + xrow)*DD + dbase + xkg*4];
            #pragma unroll
            for (int j = 0; j < 4; j++) {
                int idx = tid + j*256;
                wr[j] = *(const float4*)&W[(size_t)(dbase + (idx>>5))*DD + c0 + (idx&31)*4];
            }
        }

        #pragma unroll
        for (int kk = 0; kk < 32; kk++) {
            float2 xv = *(const float2*)&sx[buf][kk][2*ry];
            float4 wv4 = *(const float4*)&sw[buf][kk][cx*4];
            accA.x = fmaf(xv.x, wv4.x, accA.x);
            accA.y = fmaf(xv.x, wv4.y, accA.y);
            accA.z = fmaf(xv.x, wv4.z, accA.z);
            accA.w = fmaf(xv.x, wv4.w, accA.w);
            accB.x = fmaf(xv.y, wv4.x, accB.x);
            accB.y = fmaf(xv.y, wv4.y, accB.y);
            accB.z = fmaf(xv.y, wv4.z, accB.z);
            accB.w = fmaf(xv.y, wv4.w, accB.w);
        }

        if (c < 7) {
            int nbuf = buf ^ 1;
            if (tid < 128) {
                sx[nbuf][xkg*4+0][xrow] = xr.x;
                sx[nbuf][xkg*4+1][xrow] = xr.y;
                sx[nbuf][xkg*4+2][xrow] = xr.z;
                sx[nbuf][xkg*4+3][xrow] = xr.w;
            }
            #pragma unroll
            for (int j = 0; j < 4; j++) {
                int idx = tid + j*256;
                *(float4*)&sw[nbuf][idx>>5][(idx&31)*4] = wr[j];
            }
        }
        __syncthreads();
    }

    float4* dst4 = (float4*)dst;
    size_t obase = (size_t)(r0 + 2*ry) * 64 + (c0 >> 2) + cx;
    dst4[obase]      = accA;
    dst4[obase + 64] = accB;
}

// ---------------------------------------------------------------------------
// Kernel 2: main GAT. Block = (b,h,16-row i-tile), 256 blocks, 256 thr,
// 3 blocks/SM (smem 72448B, regs<=85 via 4 f-passes). sk dropped (softmax
// invariant). sq via conflict-free diagonal dots. e -> coalesced scratch.
// ---------------------------------------------------------------------------
__global__ __launch_bounds__(256, 3) void gat_main(float* __restrict__ out_h,
                                                   const float* __restrict__ a_in)
{
    extern __shared__ float sm[];
    float* sh_e  = sm;                    // 16*516 = 8256
    float* sh_x  = sh_e + 16*516;         // 128*64 = 8192
    float* sh_hk = sh_x + 128*64;         // 16*68  = 1088
    float* sh_sq = sh_hk + 16*68;         // 512
    float* sh_aa = sh_sq + 512;           // 64
    // total 18112 floats = 72448 B

    int bid = blockIdx.x;
    int b   = bid >> 7;
    int h   = (bid >> 5) & 3;
    int i0  = (bid & 31) * 16;
    int tid = threadIdx.x;
    int lane = tid & 31;
    int wid  = tid >> 5;

    // stage hk [16 x 64] (stride 68), aa = 0.4*a
    {
        int r = tid >> 4, fgi = tid & 15;
        float4 kv = ((const float4*)(g_hk + (size_t)(b*NN + i0 + r)*HDH + h*HDD))[fgi];
        *(float4*)&sh_hk[r*68 + fgi*4] = kv;
    }
    if (tid < HDD) sh_aa[tid] = 0.4f * a_in[tid];
    __syncthreads();

    int ii = lane & 15;
    int jh = lane >> 4;

    // ---- phase A: logits over 4 hq chunks of 128 rows ----
    #pragma unroll 1
    for (int cs = 0; cs < NN; cs += 128) {
        __syncthreads();
        for (int t = tid; t < 128*16; t += 256) {
            int r = t >> 4, fgi = t & 15;
            ((float4*)sh_x)[t] =
                ((const float4*)(g_hq + (size_t)(b*NN + cs + r)*HDH + h*HDD))[fgi];
        }
        __syncthreads();

        // sq: thread pair per row, diagonal conflict-free reads, one shfl
        {
            int r  = tid >> 1;
            int f0 = (tid & 1) << 5;
            int ph = ((lane >> 1) + ((lane & 1) << 4)) & 31;
            float s = 0.f;
            #pragma unroll
            for (int k2 = 0; k2 < 32; k2++) {
                int f = f0 + ((ph + k2) & 31);
                s = fmaf(sh_aa[f], sh_x[r*64 + f], s);
            }
            s += __shfl_xor_sync(0xffffffffu, s, 1);
            if ((tid & 1) == 0) sh_sq[cs + r] = 1.5f * s;
        }
        __syncthreads();

        float accj[8];
        #pragma unroll 1
        for (int pass = 0; pass < 4; pass++) {
            ull kr[8], aw[8];
            {
                const ulonglong2* kp = (const ulonglong2*)(sh_hk + ii*68 + pass*16);
                const ulonglong2* ap = (const ulonglong2*)(sh_aa + pass*16);
                #pragma unroll
                for (int g = 0; g < 4; g++) {
                    ulonglong2 kk = kp[g];
                    kr[2*g] = kk.x; kr[2*g+1] = kk.y;
                    ulonglong2 av = ap[g];
                    aw[2*g] = av.x; aw[2*g+1] = av.y;
                }
            }
            #pragma unroll
            for (int t = 0; t < 8; t++) {
                int jj = wid*16 + t*2 + jh;
                const ulonglong2* q2 = (const ulonglong2*)(sh_x + jj*64 + pass*16);
                ull acc0 = 0ULL, acc1 = 0ULL;
                #pragma unroll
                for (int g = 0; g < 4; g++) {
                    ulonglong2 qq = q2[g];
                    ull t0 = add2(qq.x, kr[2*g]) & ABS2;
                    acc0 = fma2(aw[2*g], t0, acc0);
                    ull t1 = add2(qq.y, kr[2*g+1]) & ABS2;
                    acc1 = fma2(aw[2*g+1], t1, acc1);
                }
                float2 a0 = unpack2(acc0), a1 = unpack2(acc1);
                float s = (a0.x + a0.y) + (a1.x + a1.y);
                if (pass == 0) accj[t] = s;
                else           accj[t] += s;
            }
        }
        #pragma unroll
        for (int t = 0; t < 8; t++) {
            int j = cs + wid*16 + t*2 + jh;
            sh_e[ii*516 + j] = accj[t] + sh_sq[j];
        }
    }
    __syncthreads();

    // ---- phase B: row softmax (warp w -> rows 2w, 2w+1) ----
    #pragma unroll
    for (int rr = 0; rr < 2; rr++) {
        float* row = sh_e + (2*wid + rr)*516;
        float mx = -1e30f;
        for (int j = lane; j < NN; j += 32) mx = fmaxf(mx, row[j]);
        #pragma unroll
        for (int o = 16; o; o >>= 1) mx = fmaxf(mx, __shfl_xor_sync(0xffffffffu, mx, o));
        float s = 0.f;
        for (int j = lane; j < NN; j += 32) {
            float ex = __expf(row[j] - mx);
            row[j] = ex;
            s += ex;
        }
        #pragma unroll
        for (int o = 16; o; o >>= 1) s += __shfl_xor_sync(0xffffffffu, s, o);
        float inv = 1.f / s;
        for (int j = lane; j < NN; j += 32) row[j] *= inv;
    }
    __syncthreads();

    // ---- phase C1: write e to scratch [B,H,N,N] — coalesced float4 ----
    {
        float* ebase = g_es + ((size_t)(b*HH + h)*NN + i0)*NN;
        for (int t = tid; t < 16*128; t += 256) {
            int i = t >> 7, jg = t & 127;
            *(float4*)&ebase[(size_t)i*NN + jg*4] = *(const float4*)&sh_e[i*516 + jg*4];
        }
    }

    // ---- phase C2: AV over 4 hv chunks; warp -> 2 rows, full j ----
    {
        int r0 = 2*wid + (lane >> 4);
        int fg = lane & 15;

        ull a00 = 0ULL, a01 = 0ULL;

        #pragma unroll 1
        for (int cs = 0; cs < NN; cs += 128) {
            __syncthreads();
            for (int t = tid; t < 128*16; t += 256) {
                int r = t >> 4, fgi = t & 15;
                ((float4*)sh_x)[t] =
                    ((const float4*)(g_hv + (size_t)(b*NN + cs + r)*HDH + h*HDD))[fgi];
            }
            __syncthreads();

            #pragma unroll 4
            for (int jj = 0; jj < 128; jj += 4) {
                float4 e0 = *(const float4*)&sh_e[r0*516 + cs + jj];
                {
                    ulonglong2 vv = *(const ulonglong2*)(sh_x + (jj+0)*64 + fg*4);
                    ull ev = pack2(e0.x, e0.x);
                    a00 = fma2(ev, vv.x, a00); a01 = fma2(ev, vv.y, a01);
                }
                {
                    ulonglong2 vv = *(const ulonglong2*)(sh_x + (jj+1)*64 + fg*4);
                    ull ev = pack2(e0.y, e0.y);
                    a00 = fma2(ev, vv.x, a00); a01 = fma2(ev, vv.y, a01);
                }
                {
                    ulonglong2 vv = *(const ulonglong2*)(sh_x + (jj+2)*64 + fg*4);
                    ull ev = pack2(e0.z, e0.z);
                    a00 = fma2(ev, vv.x, a00); a01 = fma2(ev, vv.y, a01);
                }
                {
                    ulonglong2 vv = *(const ulonglong2*)(sh_x + (jj+3)*64 + fg*4);
                    ull ev = pack2(e0.w, e0.w);
                    a00 = fma2(ev, vv.x, a00); a01 = fma2(ev, vv.y, a01);
                }
            }
        }
        float2 f0 = unpack2(a00), f1 = unpack2(a01);
        float4 ra = make_float4(fmaxf(f0.x,0.f), fmaxf(f0.y,0.f),
                                fmaxf(f1.x,0.f), fmaxf(f1.y,0.f));
        *(float4*)&out_h[(size_t)(b*NN + i0 + r0)*HDH + h*HDD + fg*4] = ra;
    }
}

// ---------------------------------------------------------------------------
// Kernel 3: e transpose  [B,H,N,N] scratch -> [B,N,N,H] output (coalesced)
// ---------------------------------------------------------------------------
__global__ __launch_bounds__(256) void e_trans(float* __restrict__ out_e)
{
    int gid = blockIdx.x * 256 + threadIdx.x;    // grid 512 -> 131072 threads
    #pragma unroll
    for (int rep = 0; rep < 4; rep++) {
        int idx = gid + rep * 131072;            // 0..524287 = (b, i*N+j)
        int b  = idx >> 18;
        int ij = idx & 262143;
        const float* p = g_es + (size_t)b * (HH*NN*NN) + ij;
        float4 v = make_float4(p[0], p[NN*NN], p[2*NN*NN], p[3*NN*NN]);
        *(float4*)&out_e[(size_t)idx * 4] = v;
    }
}

// ---------------------------------------------------------------------------
extern "C" void kernel_launch(void* const* d_in, const int* in_sizes, int n_in,
                              void* d_out, int out_size)
{
    const float* q  = (const float*)d_in[0];
    const float* k  = (const float*)d_in[1];
    const float* v  = (const float*)d_in[2];
    const float* wq = (const float*)d_in[3];
    const float* bq = (const float*)d_in[4];
    const float* wv = (const float*)d_in[5];
    const float* bv = (const float*)d_in[6];
    const float* a  = (const float*)d_in[7];

    float* out_h = (float*)d_out;
    float* out_e = out_h + (size_t)BB*NN*HDH;

    const int smem_main = (16*516 + 128*64 + 16*68 + 512 + 64) * (int)sizeof(float); // 72448
    cudaFuncSetAttribute(gat_main, cudaFuncAttributeMaxDynamicSharedMemorySize, smem_main);

    proj_kernel<<<384, 256>>>(q, k, v, wq, bq, wv, bv);
    gat_main<<<256, 256, smem_main>>>(out_h, a);
    e_trans<<<512, 256>>>(out_e);
}

// round 9
// speedup vs baseline: 1.1813x; 1.1813x over previous
#include <cuda_runtime.h>

#define BB   2
#define NN   512
#define DD   256
#define HH   4
#define HDD  64
#define HDH  256

typedef unsigned long long ull;
#define ABS2 0x7fffffff7fffffffULL

__device__ __align__(16) float g_hq[BB*NN*HDH];
__device__ __align__(16) float g_hk[BB*NN*HDH];
__device__ __align__(16) float g_hv[BB*NN*HDH];
__device__ __align__(16) float g_sq[BB*NN*HH];
__device__ __align__(16) float g_aa[HDD];

__device__ __forceinline__ ull add2(ull a, ull b) {
    ull r; asm("add.rn.f32x2 %0, %1, %2;" : "=l"(r) : "l"(a), "l"(b)); return r;
}
__device__ __forceinline__ ull fma2(ull a, ull b, ull c) {
    ull r; asm("fma.rn.f32x2 %0, %1, %2, %3;" : "=l"(r) : "l"(a), "l"(b), "l"(c)); return r;
}
__device__ __forceinline__ ull pack2(float lo, float hi) {
    ull r; asm("mov.b64 %0, {%1, %2};" : "=l"(r) : "f"(lo), "f"(hi)); return r;
}
__device__ __forceinline__ float2 unpack2(ull v) {
    float2 f; asm("mov.b64 {%0, %1}, %2;" : "=f"(f.x), "=f"(f.y) : "l"(v)); return f;
}

// ---------------------------------------------------------------------------
// Kernel 1: projections — EXACT round-3 version (best measured: 22.9us).
// Block tile 32x128, 192 blocks, 256 threads, k-chunk 16 double-buffered.
// ---------------------------------------------------------------------------
__global__ __launch_bounds__(256) void proj_kernel(
    const float* __restrict__ q, const float* __restrict__ k, const float* __restrict__ v,
    const float* __restrict__ wq, const float* __restrict__ bq,
    const float* __restrict__ wv, const float* __restrict__ bv)
{
    __shared__ float sx[2][16][36];
    __shared__ float sw[2][16][128];

    int bid = blockIdx.x;
    int m  = bid >> 6;
    int rt = (bid >> 1) & 31;
    int ct = bid & 1;
    int r0 = rt * 32, c0 = ct * 128;

    const float* src  = (m==0) ? q : (m==1) ? k : v;
    const float* W    = (m<2)  ? wq : wv;
    const float* bias = (m<2)  ? bq : bv;
    float* dst        = (m==0) ? g_hq : (m==1) ? g_hk : g_hv;

    int tid = threadIdx.x;
    int ry  = tid >> 5;
    int cx  = tid & 31;

    float4 b4 = *(const float4*)&bias[c0 + cx*4];
    float4 acc0 = b4, acc1 = b4, acc2 = b4, acc3 = b4;

    int xrow = tid >> 2, xdg = tid & 3;
    int wd0 = tid >> 5,          wc0 = tid & 31;
    int wd1 = (tid + 256) >> 5,  wc1 = tid & 31;

    float4 xr = make_float4(0.f,0.f,0.f,0.f);
    if (tid < 128) xr = *(const float4*)&src[(size_t)(r0 + xrow)*DD + xdg*4];
    float4 wr0 = *(const float4*)&W[(size_t)wd0*DD + c0 + wc0*4];
    float4 wr1 = *(const float4*)&W[(size_t)wd1*DD + c0 + wc1*4];

    if (tid < 128) {
        sx[0][xdg*4+0][xrow] = xr.x;
        sx[0][xdg*4+1][xrow] = xr.y;
        sx[0][xdg*4+2][xrow] = xr.z;
        sx[0][xdg*4+3][xrow] = xr.w;
    }
    *(float4*)&sw[0][wd0][wc0*4] = wr0;
    *(float4*)&sw[0][wd1][wc1*4] = wr1;
    __syncthreads();

    #pragma unroll 1
    for (int c = 0; c < 16; c++) {
        int buf = c & 1;
        if (c < 15) {
            int dbase = (c + 1) * 16;
            if (tid < 128) xr = *(const float4*)&src[(size_t)(r0 + xrow)*DD + dbase + xdg*4];
            wr0 = *(const float4*)&W[(size_t)(dbase + wd0)*DD + c0 + wc0*4];
            wr1 = *(const float4*)&W[(size_t)(dbase + wd1)*DD + c0 + wc1*4];
        }

        #pragma unroll
        for (int kk = 0; kk < 16; kk++) {
            float4 xv = *(const float4*)&sx[buf][kk][ry*4];
            float4 wv = *(const float4*)&sw[buf][kk][cx*4];
            acc0.x = fmaf(xv.x, wv.x, acc0.x);
            acc0.y = fmaf(xv.x, wv.y, acc0.y);
            acc0.z = fmaf(xv.x, wv.z, acc0.z);
            acc0.w = fmaf(xv.x, wv.w, acc0.w);
            acc1.x = fmaf(xv.y, wv.x, acc1.x);
            acc1.y = fmaf(xv.y, wv.y, acc1.y);
            acc1.z = fmaf(xv.y, wv.z, acc1.z);
            acc1.w = fmaf(xv.y, wv.w, acc1.w);
            acc2.x = fmaf(xv.z, wv.x, acc2.x);
            acc2.y = fmaf(xv.z, wv.y, acc2.y);
            acc2.z = fmaf(xv.z, wv.z, acc2.z);
            acc2.w = fmaf(xv.z, wv.w, acc2.w);
            acc3.x = fmaf(xv.w, wv.x, acc3.x);
            acc3.y = fmaf(xv.w, wv.y, acc3.y);
            acc3.z = fmaf(xv.w, wv.z, acc3.z);
            acc3.w = fmaf(xv.w, wv.w, acc3.w);
        }

        if (c < 15) {
            int nbuf = buf ^ 1;
            if (tid < 128) {
                sx[nbuf][xdg*4+0][xrow] = xr.x;
                sx[nbuf][xdg*4+1][xrow] = xr.y;
                sx[nbuf][xdg*4+2][xrow] = xr.z;
                sx[nbuf][xdg*4+3][xrow] = xr.w;
            }
            *(float4*)&sw[nbuf][wd0][wc0*4] = wr0;
            *(float4*)&sw[nbuf][wd1][wc1*4] = wr1;
        }
        __syncthreads();
    }

    float4* dst4 = (float4*)dst;
    size_t obase = (size_t)(r0 + ry*4) * 64 + (c0 >> 2) + cx;
    dst4[obase + 0*64] = acc0;
    dst4[obase + 1*64] = acc1;
    dst4[obase + 2*64] = acc2;
    dst4[obase + 3*64] = acc3;
}

// ---------------------------------------------------------------------------
// Kernel 2: base — sq only (sk dropped: softmax shift-invariance) + aa=0.4*a
// ---------------------------------------------------------------------------
__global__ __launch_bounds__(128) void base_kernel(const float* __restrict__ a)
{
    int n = blockIdx.x;                 // b*N + j, 1024 blocks
    if (n == 0 && threadIdx.x < HDD) g_aa[threadIdx.x] = 0.4f * a[threadIdx.x];

    int w = threadIdx.x >> 5, lane = threadIdx.x & 31;
    const float* row = g_hq + (size_t)n*HDH + w*HDD;
    float s = fmaf(a[lane], row[lane], a[lane+32] * row[lane+32]);
    #pragma unroll
    for (int o = 16; o; o >>= 1) s += __shfl_xor_sync(0xffffffffu, s, o);
    if (lane == 0) g_sq[n*HH + w] = 0.6f * s;
}

// ---------------------------------------------------------------------------
// Kernel 3: main GAT — EXACT round-6-benched structure (best: ~40us), minus sk.
// Block per (b,h,16-row i-tile) = 256 blocks, 256 thr, 2 blocks/SM, 2-pass.
// ---------------------------------------------------------------------------
__global__ __launch_bounds__(256, 2) void gat_main(float* __restrict__ out_h,
                                                   float* __restrict__ out_e)
{
    extern __shared__ float sm[];
    float* sh_e  = sm;                    // 16*516
    float* sh_x  = sh_e + 16*516;         // 128*64
    float* sh_hk = sh_x + 128*64;         // 16*68
    float* sh_sq = sh_hk + 16*68;         // 512
    float* sh_p  = sh_sq + 512;           // 16*64
    float* sh_aa = sh_p + 16*64;          // 64
    // total 19136 floats = 76544 B

    int bid = blockIdx.x;
    int b   = bid >> 7;
    int h   = (bid >> 5) & 3;
    int i0  = (bid & 31) * 16;
    int tid = threadIdx.x;
    int lane = tid & 31;
    int wid  = tid >> 5;

    {
        int r = tid >> 4, fgi = tid & 15;
        float4 kv = ((const float4*)(g_hk + (size_t)(b*NN + i0 + r)*HDH + h*HDD))[fgi];
        *(float4*)&sh_hk[r*68 + fgi*4] = kv;
    }
    for (int t = tid; t < NN; t += 256)
        sh_sq[t] = g_sq[(b*NN + t)*HH + h];
    if (tid < 16) ((float4*)sh_aa)[tid] = ((const float4*)g_aa)[tid];
    __syncthreads();

    int ii = lane & 15;
    int jh = lane >> 4;

    // ---- phase A: logits over 4 hq chunks of 128 rows ----
    #pragma unroll 1
    for (int cs = 0; cs < NN; cs += 128) {
        __syncthreads();
        for (int t = tid; t < 128*16; t += 256) {
            int r = t >> 4, fgi = t & 15;
            ((float4*)sh_x)[t] =
                ((const float4*)(g_hq + (size_t)(b*NN + cs + r)*HDH + h*HDD))[fgi];
        }
        __syncthreads();

        float accj[8];
        #pragma unroll 1
        for (int pass = 0; pass < 2; pass++) {
            ull kr[16], aw[16];
            {
                const ulonglong2* kp = (const ulonglong2*)(sh_hk + ii*68 + pass*32);
                const ulonglong2* ap = (const ulonglong2*)(sh_aa + pass*32);
                #pragma unroll
                for (int g = 0; g < 8; g++) {
                    ulonglong2 kk = kp[g];
                    kr[2*g] = kk.x; kr[2*g+1] = kk.y;
                    ulonglong2 av = ap[g];
                    aw[2*g] = av.x; aw[2*g+1] = av.y;
                }
            }
            #pragma unroll 2
            for (int t = 0; t < 8; t++) {
                int jj = wid*16 + t*2 + jh;
                const ulonglong2* q2 = (const ulonglong2*)(sh_x + jj*64 + pass*32);
                ull acc0 = 0ULL, acc1 = 0ULL;
                #pragma unroll
                for (int g = 0; g < 8; g++) {
                    ulonglong2 qq = q2[g];
                    ull t0 = add2(qq.x, kr[2*g]) & ABS2;
                    acc0 = fma2(aw[2*g], t0, acc0);
                    ull t1 = add2(qq.y, kr[2*g+1]) & ABS2;
                    acc1 = fma2(aw[2*g+1], t1, acc1);
                }
                float2 a0 = unpack2(acc0), a1 = unpack2(acc1);
                float s = (a0.x + a0.y) + (a1.x + a1.y);
                if (pass == 0) accj[t] = s;
                else           accj[t] += s;
            }
        }
        #pragma unroll
        for (int t = 0; t < 8; t++) {
            int j = cs + wid*16 + t*2 + jh;
            sh_e[ii*516 + j] = accj[t] + sh_sq[j];
        }
    }
    __syncthreads();

    // ---- phase B: row softmax (warp w -> rows 2w, 2w+1) ----
    #pragma unroll
    for (int rr = 0; rr < 2; rr++) {
        float* row = sh_e + (2*wid + rr)*516;
        float mx = -1e30f;
        for (int j = lane; j < NN; j += 32) mx = fmaxf(mx, row[j]);
        #pragma unroll
        for (int o = 16; o; o >>= 1) mx = fmaxf(mx, __shfl_xor_sync(0xffffffffu, mx, o));
        float s = 0.f;
        for (int j = lane; j < NN; j += 32) {
            float ex = __expf(row[j] - mx);
            row[j] = ex;
            s += ex;
        }
        #pragma unroll
        for (int o = 16; o; o >>= 1) s += __shfl_xor_sync(0xffffffffu, s, o);
        float inv = 1.f / s;
        for (int j = lane; j < NN; j += 32) row[j] *= inv;
    }
    __syncthreads();

    // ---- phase C1: write e [B,N,N,H] ----
    {
        float* ebase = out_e + ((size_t)(b*NN + i0) * NN) * HH + h;
        for (int t = tid; t < 16*512; t += 256) {
            int i = t >> 9, j = t & 511;
            ebase[(size_t)(i*NN + j) * HH] = sh_e[i*516 + j];
        }
    }

    // ---- phase C2: AV over 4 hv chunks; warps split j halves; smem reduce ----
    {
        int wq = wid & 3;
        int jhalf = wid >> 2;
        int r0 = 2*wq + (lane >> 4);
        int r1 = r0 + 8;
        int fg = lane & 15;

        ull a00 = 0ULL, a01 = 0ULL, a10 = 0ULL, a11 = 0ULL;

        #pragma unroll 1
        for (int cs = 0; cs < NN; cs += 128) {
            __syncthreads();
            for (int t = tid; t < 128*16; t += 256) {
                int r = t >> 4, fgi = t & 15;
                ((float4*)sh_x)[t] =
                    ((const float4*)(g_hv + (size_t)(b*NN + cs + r)*HDH + h*HDD))[fgi];
            }
            __syncthreads();

            int jb = jhalf * 64;
            #pragma unroll 2
            for (int qv = 0; qv < 64; qv += 4) {
                int jj = jb + qv;
                float4 e0 = *(const float4*)&sh_e[r0*516 + cs + jj];
                float4 e1 = *(const float4*)&sh_e[r1*516 + cs + jj];
                {
                    ulonglong2 vv = *(const ulonglong2*)(sh_x + (jj+0)*64 + fg*4);
                    ull ev0 = pack2(e0.x, e0.x), ev1 = pack2(e1.x, e1.x);
                    a00 = fma2(ev0, vv.x, a00); a01 = fma2(ev0, vv.y, a01);
                    a10 = fma2(ev1, vv.x, a10); a11 = fma2(ev1, vv.y, a11);
                }
                {
                    ulonglong2 vv = *(const ulonglong2*)(sh_x + (jj+1)*64 + fg*4);
                    ull ev0 = pack2(e0.y, e0.y), ev1 = pack2(e1.y, e1.y);
                    a00 = fma2(ev0, vv.x, a00); a01 = fma2(ev0, vv.y, a01);
                    a10 = fma2(ev1, vv.x, a10); a11 = fma2(ev1, vv.y, a11);
                }
                {
                    ulonglong2 vv = *(const ulonglong2*)(sh_x + (jj+2)*64 + fg*4);
                    ull ev0 = pack2(e0.z, e0.z), ev1 = pack2(e1.z, e1.z);
                    a00 = fma2(ev0, vv.x, a00); a01 = fma2(ev0, vv.y, a01);
                    a10 = fma2(ev1, vv.x, a10); a11 = fma2(ev1, vv.y, a11);
                }
                {
                    ulonglong2 vv = *(const ulonglong2*)(sh_x + (jj+3)*64 + fg*4);
                    ull ev0 = pack2(e0.w, e0.w), ev1 = pack2(e1.w, e1.w);
                    a00 = fma2(ev0, vv.x, a00); a01 = fma2(ev0, vv.y, a01);
                    a10 = fma2(ev1, vv.x, a10); a11 = fma2(ev1, vv.y, a11);
                }
            }
        }
        __syncthreads();
        if (jhalf == 1) {
            *(ulonglong2*)&sh_p[r0*64 + fg*4] = make_ulonglong2(a00, a01);
            *(ulonglong2*)&sh_p[r1*64 + fg*4] = make_ulonglong2(a10, a11);
        }
        __syncthreads();
        if (jhalf == 0) {
            ulonglong2 p0 = *(const ulonglong2*)&sh_p[r0*64 + fg*4];
            ulonglong2 p1 = *(const ulonglong2*)&sh_p[r1*64 + fg*4];
            a00 = add2(a00, p0.x); a01 = add2(a01, p0.y);
            a10 = add2(a10, p1.x); a11 = add2(a11, p1.y);
            float2 f0 = unpack2(a00), f1 = unpack2(a01);
            float2 f2 = unpack2(a10), f3 = unpack2(a11);
            float4 ra = make_float4(fmaxf(f0.x,0.f), fmaxf(f0.y,0.f),
                                    fmaxf(f1.x,0.f), fmaxf(f1.y,0.f));
            float4 rb = make_float4(fmaxf(f2.x,0.f), fmaxf(f2.y,0.f),
                                    fmaxf(f3.x,0.f), fmaxf(f3.y,0.f));
            *(float4*)&out_h[(size_t)(b*NN + i0 + r0)*HDH + h*HDD + fg*4] = ra;
            *(float4*)&out_h[(size_t)(b*NN + i0 + r1)*HDH + h*HDD + fg*4] = rb;
        }
    }
}

// ---------------------------------------------------------------------------
extern "C" void kernel_launch(void* const* d_in, const int* in_sizes, int n_in,
                              void* d_out, int out_size)
{
    const float* q  = (const float*)d_in[0];
    const float* k  = (const float*)d_in[1];
    const float* v  = (const float*)d_in[2];
    const float* wq = (const float*)d_in[3];
    const float* bq = (const float*)d_in[4];
    const float* wv = (const float*)d_in[5];
    const float* bv = (const float*)d_in[6];
    const float* a  = (const float*)d_in[7];

    float* out_h = (float*)d_out;
    float* out_e = out_h + (size_t)BB*NN*HDH;

    const int smem_main = (16*516 + 128*64 + 16*68 + 512 + 16*64 + 64) * (int)sizeof(float); // 76544
    cudaFuncSetAttribute(gat_main, cudaFuncAttributeMaxDynamicSharedMemorySize, smem_main);

    proj_kernel<<<192, 256>>>(q, k, v, wq, bq, wv, bv);
    base_kernel<<<1024, 128>>>(a);
    gat_main<<<256, 256, smem_main>>>(out_h, out_e);
}

// round 10
// speedup vs baseline: 1.2185x; 1.0315x over previous
#include <cuda_runtime.h>

#define BB   2
#define NN   512
#define DD   256
#define HH   4
#define HDD  64
#define HDH  256

typedef unsigned long long ull;
#define ABS2 0x7fffffff7fffffffULL

__device__ __align__(16) float g_hq[BB*NN*HDH];
__device__ __align__(16) float g_hk[BB*NN*HDH];
__device__ __align__(16) float g_hv[BB*NN*HDH];
__device__ __align__(16) float g_sq[BB*NN*HH];
__device__ __align__(16) float g_aa[HDD];

__device__ __forceinline__ ull add2(ull a, ull b) {
    ull r; asm("add.rn.f32x2 %0, %1, %2;" : "=l"(r) : "l"(a), "l"(b)); return r;
}
__device__ __forceinline__ ull fma2(ull a, ull b, ull c) {
    ull r; asm("fma.rn.f32x2 %0, %1, %2, %3;" : "=l"(r) : "l"(a), "l"(b), "l"(c)); return r;
}
__device__ __forceinline__ ull pack2(float lo, float hi) {
    ull r; asm("mov.b64 %0, {%1, %2};" : "=l"(r) : "f"(lo), "f"(hi)); return r;
}
__device__ __forceinline__ float2 unpack2(ull v) {
    float2 f; asm("mov.b64 {%0, %1}, %2;" : "=f"(f.x), "=f"(f.y) : "l"(v)); return f;
}
__device__ __forceinline__ void cp16(unsigned s, const void* g) {
    asm volatile("cp.async.ca.shared.global [%0], [%1], 16;" :: "r"(s), "l"(g));
}
#define CP_COMMIT() asm volatile("cp.async.commit_group;")
#define CP_WAIT1()  asm volatile("cp.async.wait_group 1;")
#define CP_WAIT0()  asm volatile("cp.async.wait_group 0;")

// ---------------------------------------------------------------------------
// Kernel 1: projections — r3 inner math (4x4 thread tile, fma/crossbar
// balanced) at 16x128 tiles / 128 threads -> 384 balanced blocks (3/SM).
// ---------------------------------------------------------------------------
__global__ __launch_bounds__(128) void proj_kernel(
    const float* __restrict__ q, const float* __restrict__ k, const float* __restrict__ v,
    const float* __restrict__ wq, const float* __restrict__ bq,
    const float* __restrict__ wv, const float* __restrict__ bv)
{
    __shared__ float sx[2][16][20];    // 16 rows, stride 20 floats (80B, 16B-aligned)
    __shared__ float sw[2][16][128];

    int bid = blockIdx.x;
    int m   = bid >> 7;            // 0=q,1=k,2=v
    int rem = bid & 127;
    int rt  = rem >> 1;            // 64 row tiles of 16
    int ct  = rem & 1;             // 2 col tiles of 128
    int r0 = rt * 16, c0 = ct * 128;

    const float* src  = (m==0) ? q : (m==1) ? k : v;
    const float* W    = (m<2)  ? wq : wv;
    const float* bias = (m<2)  ? bq : bv;
    float* dst        = (m==0) ? g_hq : (m==1) ? g_hk : g_hv;

    int tid = threadIdx.x;
    int ry  = tid >> 5;    // 0..3 -> rows ry*4 .. ry*4+3
    int cx  = tid & 31;    // cols cx*4 .. cx*4+3

    float4 b4 = *(const float4*)&bias[c0 + cx*4];
    float4 acc0 = b4, acc1 = b4, acc2 = b4, acc3 = b4;

    int xrow = tid >> 2, xdg = tid & 3;     // threads 0..63: x float4

    // prefetch chunk 0
    float4 xr = make_float4(0.f,0.f,0.f,0.f);
    if (tid < 64) xr = *(const float4*)&src[(size_t)(r0 + xrow)*DD + xdg*4];
    float4 wr[4];
    #pragma unroll
    for (int j = 0; j < 4; j++) {
        int idx = tid + j*128;
        wr[j] = *(const float4*)&W[(size_t)(idx>>5)*DD + c0 + (idx&31)*4];
    }

    if (tid < 64) {
        sx[0][xdg*4+0][xrow] = xr.x;
        sx[0][xdg*4+1][xrow] = xr.y;
        sx[0][xdg*4+2][xrow] = xr.z;
        sx[0][xdg*4+3][xrow] = xr.w;
    }
    #pragma unroll
    for (int j = 0; j < 4; j++) {
        int idx = tid + j*128;
        *(float4*)&sw[0][idx>>5][(idx&31)*4] = wr[j];
    }
    __syncthreads();

    #pragma unroll 1
    for (int c = 0; c < 16; c++) {
        int buf = c & 1;
        if (c < 15) {
            int dbase = (c + 1) * 16;
            if (tid < 64) xr = *(const float4*)&src[(size_t)(r0 + xrow)*DD + dbase + xdg*4];
            #pragma unroll
            for (int j = 0; j < 4; j++) {
                int idx = tid + j*128;
                wr[j] = *(const float4*)&W[(size_t)(dbase + (idx>>5))*DD + c0 + (idx&31)*4];
            }
        }

        #pragma unroll
        for (int kk = 0; kk < 16; kk++) {
            float4 xv = *(const float4*)&sx[buf][kk][ry*4];   // warp broadcast
            float4 wv = *(const float4*)&sw[buf][kk][cx*4];   // conflict-free
            acc0.x = fmaf(xv.x, wv.x, acc0.x);
            acc0.y = fmaf(xv.x, wv.y, acc0.y);
            acc0.z = fmaf(xv.x, wv.z, acc0.z);
            acc0.w = fmaf(xv.x, wv.w, acc0.w);
            acc1.x = fmaf(xv.y, wv.x, acc1.x);
            acc1.y = fmaf(xv.y, wv.y, acc1.y);
            acc1.z = fmaf(xv.y, wv.z, acc1.z);
            acc1.w = fmaf(xv.y, wv.w, acc1.w);
            acc2.x = fmaf(xv.z, wv.x, acc2.x);
            acc2.y = fmaf(xv.z, wv.y, acc2.y);
            acc2.z = fmaf(xv.z, wv.z, acc2.z);
            acc2.w = fmaf(xv.z, wv.w, acc2.w);
            acc3.x = fmaf(xv.w, wv.x, acc3.x);
            acc3.y = fmaf(xv.w, wv.y, acc3.y);
            acc3.z = fmaf(xv.w, wv.z, acc3.z);
            acc3.w = fmaf(xv.w, wv.w, acc3.w);
        }

        if (c < 15) {
            int nbuf = buf ^ 1;
            if (tid < 64) {
                sx[nbuf][xdg*4+0][xrow] = xr.x;
                sx[nbuf][xdg*4+1][xrow] = xr.y;
                sx[nbuf][xdg*4+2][xrow] = xr.z;
                sx[nbuf][xdg*4+3][xrow] = xr.w;
            }
            #pragma unroll
            for (int j = 0; j < 4; j++) {
                int idx = tid + j*128;
                *(float4*)&sw[nbuf][idx>>5][(idx&31)*4] = wr[j];
            }
        }
        __syncthreads();
    }

    float4* dst4 = (float4*)dst;
    size_t obase = (size_t)(r0 + ry*4) * 64 + (c0 >> 2) + cx;
    dst4[obase + 0*64] = acc0;
    dst4[obase + 1*64] = acc1;
    dst4[obase + 2*64] = acc2;
    dst4[obase + 3*64] = acc3;
}

// ---------------------------------------------------------------------------
// Kernel 2: base — sq only + aa = 0.4*a
// ---------------------------------------------------------------------------
__global__ __launch_bounds__(128) void base_kernel(const float* __restrict__ a)
{
    int n = blockIdx.x;
    if (n == 0 && threadIdx.x < HDD) g_aa[threadIdx.x] = 0.4f * a[threadIdx.x];

    int w = threadIdx.x >> 5, lane = threadIdx.x & 31;
    const float* row = g_hq + (size_t)n*HDH + w*HDD;
    float s = fmaf(a[lane], row[lane], a[lane+32] * row[lane+32]);
    #pragma unroll
    for (int o = 16; o; o >>= 1) s += __shfl_xor_sync(0xffffffffu, s, o);
    if (lane == 0) g_sq[n*HH + w] = 0.6f * s;
}

// ---------------------------------------------------------------------------
// Kernel 3: main GAT — r9 structure + cp.async double-buffered chunk staging
// (sh_x = 2 x 128x64 buffers; 109312B smem, still 2 blocks/SM).
// ---------------------------------------------------------------------------
__global__ __launch_bounds__(256, 2) void gat_main(float* __restrict__ out_h,
                                                   float* __restrict__ out_e)
{
    extern __shared__ float sm[];
    float* sh_e  = sm;                    // 16*516  = 8256
    float* sh_x  = sh_e + 16*516;         // 2*128*64 = 16384 (double buffer)
    float* sh_hk = sh_x + 2*128*64;       // 16*68   = 1088
    float* sh_sq = sh_hk + 16*68;         // 512
    float* sh_p  = sh_sq + 512;           // 16*64   = 1024
    float* sh_aa = sh_p + 16*64;          // 64
    // total 27328 floats = 109312 B

    int bid = blockIdx.x;
    int b   = bid >> 7;
    int h   = (bid >> 5) & 3;
    int i0  = (bid & 31) * 16;
    int tid = threadIdx.x;
    int lane = tid & 31;
    int wid  = tid >> 5;

    unsigned xsb = (unsigned)__cvta_generic_to_shared(sh_x);
    int sr = tid >> 4, sf = tid & 15;     // staging: 16 rows x 16 fgroups per 256-thr pass

    // prologue: async-fetch hq chunk 0 into buffer 0 (overlaps hk/sq staging)
    {
        const float* gsrc = g_hq + (size_t)(b*NN)*HDH + h*HDD;
        #pragma unroll
        for (int rr = 0; rr < 8; rr++) {
            int r = rr*16 + sr;
            cp16(xsb + (unsigned)((r*16 + sf)*16), gsrc + (size_t)r*HDH + sf*4);
        }
        CP_COMMIT();
    }

    // stage hk [16 x 64] (stride 68), sq[512], aa[64]
    {
        int r = tid >> 4, fgi = tid & 15;
        float4 kv = ((const float4*)(g_hk + (size_t)(b*NN + i0 + r)*HDH + h*HDD))[fgi];
        *(float4*)&sh_hk[r*68 + fgi*4] = kv;
    }
    for (int t = tid; t < NN; t += 256)
        sh_sq[t] = g_sq[(b*NN + t)*HH + h];
    if (tid < 16) ((float4*)sh_aa)[tid] = ((const float4*)g_aa)[tid];

    int ii = lane & 15;
    int jh = lane >> 4;

    // ---- phase A: logits over 4 hq chunks of 128 rows, pipelined ----
    #pragma unroll 1
    for (int c = 0; c < 4; c++) {
        if (c < 3) {
            const float* gsrc = g_hq + (size_t)(b*NN + (c+1)*128)*HDH + h*HDD;
            unsigned boff = (unsigned)(((c+1)&1) * 32768);
            #pragma unroll
            for (int rr = 0; rr < 8; rr++) {
                int r = rr*16 + sr;
                cp16(xsb + boff + (unsigned)((r*16 + sf)*16), gsrc + (size_t)r*HDH + sf*4);
            }
            CP_COMMIT();
            CP_WAIT1();
        } else {
            CP_WAIT0();
        }
        __syncthreads();

        const float* xb = sh_x + (c&1)*8192;
        int cs = c*128;

        float accj[8];
        #pragma unroll 1
        for (int pass = 0; pass < 2; pass++) {
            ull kr[16], aw[16];
            {
                const ulonglong2* kp = (const ulonglong2*)(sh_hk + ii*68 + pass*32);
                const ulonglong2* ap = (const ulonglong2*)(sh_aa + pass*32);
                #pragma unroll
                for (int g = 0; g < 8; g++) {
                    ulonglong2 kk = kp[g];
                    kr[2*g] = kk.x; kr[2*g+1] = kk.y;
                    ulonglong2 av = ap[g];
                    aw[2*g] = av.x; aw[2*g+1] = av.y;
                }
            }
            #pragma unroll 2
            for (int t = 0; t < 8; t++) {
                int jj = wid*16 + t*2 + jh;
                const ulonglong2* q2 = (const ulonglong2*)(xb + jj*64 + pass*32);
                ull acc0 = 0ULL, acc1 = 0ULL;
                #pragma unroll
                for (int g = 0; g < 8; g++) {
                    ulonglong2 qq = q2[g];
                    ull t0 = add2(qq.x, kr[2*g]) & ABS2;
                    acc0 = fma2(aw[2*g], t0, acc0);
                    ull t1 = add2(qq.y, kr[2*g+1]) & ABS2;
                    acc1 = fma2(aw[2*g+1], t1, acc1);
                }
                float2 a0 = unpack2(acc0), a1 = unpack2(acc1);
                float s = (a0.x + a0.y) + (a1.x + a1.y);
                if (pass == 0) accj[t] = s;
                else           accj[t] += s;
            }
        }
        #pragma unroll
        for (int t = 0; t < 8; t++) {
            int j = cs + wid*16 + t*2 + jh;
            sh_e[ii*516 + j] = accj[t] + sh_sq[j];
        }
        __syncthreads();
    }

    // ---- phase B: row softmax (warp w -> rows 2w, 2w+1) ----
    #pragma unroll
    for (int rr = 0; rr < 2; rr++) {
        float* row = sh_e + (2*wid + rr)*516;
        float mx = -1e30f;
        for (int j = lane; j < NN; j += 32) mx = fmaxf(mx, row[j]);
        #pragma unroll
        for (int o = 16; o; o >>= 1) mx = fmaxf(mx, __shfl_xor_sync(0xffffffffu, mx, o));
        float s = 0.f;
        for (int j = lane; j < NN; j += 32) {
            float ex = __expf(row[j] - mx);
            row[j] = ex;
            s += ex;
        }
        #pragma unroll
        for (int o = 16; o; o >>= 1) s += __shfl_xor_sync(0xffffffffu, s, o);
        float inv = 1.f / s;
        for (int j = lane; j < NN; j += 32) row[j] *= inv;
    }
    __syncthreads();

    // ---- C: issue first hv fetch, then e-writes overlap it ----
    {
        const float* gsrc = g_hv + (size_t)(b*NN)*HDH + h*HDD;
        #pragma unroll
        for (int rr = 0; rr < 8; rr++) {
            int r = rr*16 + sr;
            cp16(xsb + (unsigned)((r*16 + sf)*16), gsrc + (size_t)r*HDH + sf*4);
        }
        CP_COMMIT();
    }

    // phase C1: write e [B,N,N,H]
    {
        float* ebase = out_e + ((size_t)(b*NN + i0) * NN) * HH + h;
        for (int t = tid; t < 16*512; t += 256) {
            int i = t >> 9, j = t & 511;
            ebase[(size_t)(i*NN + j) * HH] = sh_e[i*516 + j];
        }
    }

    // phase C2: AV over 4 hv chunks (pipelined); warps split j halves
    {
        int wq = wid & 3;
        int jhalf = wid >> 2;
        int r0 = 2*wq + (lane >> 4);
        int r1 = r0 + 8;
        int fg = lane & 15;

        ull a00 = 0ULL, a01 = 0ULL, a10 = 0ULL, a11 = 0ULL;

        #pragma unroll 1
        for (int c = 0; c < 4; c++) {
            if (c < 3) {
                const float* gsrc = g_hv + (size_t)(b*NN + (c+1)*128)*HDH + h*HDD;
                unsigned boff = (unsigned)(((c+1)&1) * 32768);
                #pragma unroll
                for (int rr = 0; rr < 8; rr++) {
                    int r = rr*16 + sr;
                    cp16(xsb + boff + (unsigned)((r*16 + sf)*16), gsrc + (size_t)r*HDH + sf*4);
                }
                CP_COMMIT();
                CP_WAIT1();
            } else {
                CP_WAIT0();
            }
            __syncthreads();

            const float* xb = sh_x + (c&1)*8192;
            int cs = c*128;

            int jb = jhalf * 64;
            #pragma unroll 2
            for (int qv = 0; qv < 64; qv += 4) {
                int jj = jb + qv;
                float4 e0 = *(const float4*)&sh_e[r0*516 + cs + jj];
                float4 e1 = *(const float4*)&sh_e[r1*516 + cs + jj];
                {
                    ulonglong2 vv = *(const ulonglong2*)(xb + (jj+0)*64 + fg*4);
                    ull ev0 = pack2(e0.x, e0.x), ev1 = pack2(e1.x, e1.x);
                    a00 = fma2(ev0, vv.x, a00); a01 = fma2(ev0, vv.y, a01);
                    a10 = fma2(ev1, vv.x, a10); a11 = fma2(ev1, vv.y, a11);
                }
                {
                    ulonglong2 vv = *(const ulonglong2*)(xb + (jj+1)*64 + fg*4);
                    ull ev0 = pack2(e0.y, e0.y), ev1 = pack2(e1.y, e1.y);
                    a00 = fma2(ev0, vv.x, a00); a01 = fma2(ev0, vv.y, a01);
                    a10 = fma2(ev1, vv.x, a10); a11 = fma2(ev1, vv.y, a11);
                }
                {
                    ulonglong2 vv = *(const ulonglong2*)(xb + (jj+2)*64 + fg*4);
                    ull ev0 = pack2(e0.z, e0.z), ev1 = pack2(e1.z, e1.z);
                    a00 = fma2(ev0, vv.x, a00); a01 = fma2(ev0, vv.y, a01);
                    a10 = fma2(ev1, vv.x, a10); a11 = fma2(ev1, vv.y, a11);
                }
                {
                    ulonglong2 vv = *(const ulonglong2*)(xb + (jj+3)*64 + fg*4);
                    ull ev0 = pack2(e0.w, e0.w), ev1 = pack2(e1.w, e1.w);
                    a00 = fma2(ev0, vv.x, a00); a01 = fma2(ev0, vv.y, a01);
                    a10 = fma2(ev1, vv.x, a10); a11 = fma2(ev1, vv.y, a11);
                }
            }
            __syncthreads();
        }

        if (jhalf == 1) {
            *(ulonglong2*)&sh_p[r0*64 + fg*4] = make_ulonglong2(a00, a01);
            *(ulonglong2*)&sh_p[r1*64 + fg*4] = make_ulonglong2(a10, a11);
        }
        __syncthreads();
        if (jhalf == 0) {
            ulonglong2 p0 = *(const ulonglong2*)&sh_p[r0*64 + fg*4];
            ulonglong2 p1 = *(const ulonglong2*)&sh_p[r1*64 + fg*4];
            a00 = add2(a00, p0.x); a01 = add2(a01, p0.y);
            a10 = add2(a10, p1.x); a11 = add2(a11, p1.y);
            float2 f0 = unpack2(a00), f1 = unpack2(a01);
            float2 f2 = unpack2(a10), f3 = unpack2(a11);
            float4 ra = make_float4(fmaxf(f0.x,0.f), fmaxf(f0.y,0.f),
                                    fmaxf(f1.x,0.f), fmaxf(f1.y,0.f));
            float4 rb = make_float4(fmaxf(f2.x,0.f), fmaxf(f2.y,0.f),
                                    fmaxf(f3.x,0.f), fmaxf(f3.y,0.f));
            *(float4*)&out_h[(size_t)(b*NN + i0 + r0)*HDH + h*HDD + fg*4] = ra;
            *(float4*)&out_h[(size_t)(b*NN + i0 + r1)*HDH + h*HDD + fg*4] = rb;
        }
    }
}

// ---------------------------------------------------------------------------
extern "C" void kernel_launch(void* const* d_in, const int* in_sizes, int n_in,
                              void* d_out, int out_size)
{
    const float* q  = (const float*)d_in[0];
    const float* k  = (const float*)d_in[1];
    const float* v  = (const float*)d_in[2];
    const float* wq = (const float*)d_in[3];
    const float* bq = (const float*)d_in[4];
    const float* wv = (const float*)d_in[5];
    const float* bv = (const float*)d_in[6];
    const float* a  = (const float*)d_in[7];

    float* out_h = (float*)d_out;
    float* out_e = out_h + (size_t)BB*NN*HDH;

    const int smem_main = (16*516 + 2*128*64 + 16*68 + 512 + 16*64 + 64) * (int)sizeof(float); // 109312
    cudaFuncSetAttribute(gat_main, cudaFuncAttributeMaxDynamicSharedMemorySize, smem_main);

    proj_kernel<<<384, 128>>>(q, k, v, wq, bq, wv, bv);
    base_kernel<<<1024, 128>>>(a);
    gat_main<<<256, 256, smem_main>>>(out_h, out_e);
}